// round 14
// baseline (speedup 1.0000x reference)
#include <cuda_runtime.h>
#include <cuda_fp16.h>
#include <cuda.h>
#include <cstdint>

// ---------------------------------------------------------------------------
// MoE (AriaExperts): top-2 routing + grouped tcgen05 f16 GEMM (SwiGLU fused)
// tokens=2048, hidden=1024, inter=2048, experts=8, topk=2
//
// R14: L2-traffic reduction. BM=256 (2 M=128 m-blocks share one B tile),
// ST=2 stages of 48KB -> 96KB smem, TMEM 256 cols -> still 2 CTAs/SM.
// FC1 traffic 536->402MB, FC2 268->196MB. Producer/consumer split and the
// R13-proven tail-chain handshake unchanged. Validated MMA config unchanged.
// ---------------------------------------------------------------------------

#if defined(__CUDA_ARCH__) && \
    (defined(__CUDA_ARCH_FEAT_SM103_ALL) || \
     (defined(__CUDA_ARCH_SPECIFIC__)) || \
     (defined(__CUDA_ARCH_FAMILY_SPECIFIC__)))
#define USE_TC 1
#else
#define USE_TC 0
#endif

#define NT     2048
#define HID    1024
#define INTERD 2048
#define NE     8
#define TK     2
#define NP     (NT*TK)
#define NPP    (NP + 256)

// ---- device scratch ----
__device__ __align__(16) __half g_Xp  [NPP * HID];
__device__ __align__(16) __half g_Act [NPP * INTERD];
__device__ __align__(16) float  g_Out2[NPP * HID];
__device__ __align__(16) __half g_W1h[NE * 2 * INTERD * HID];   // [E][4096][1024] k-contig
__device__ __align__(16) __half g_W2h[NE * HID * INTERD];       // [E][1024][2048] k-contig
__device__ int   g_counts[NE];
__device__ int   g_fill[NE];
__device__ int   g_offsets[NE + 1];
__device__ int   g_tok_e[NT * TK];
__device__ float g_tok_s[NT * TK];
__device__ int   g_tok_pos[NT * TK];

// ---------------------------------------------------------------------------
// conv: weight transpose + fp32->fp16  (in [e][K][N] f32 -> out [e][N][K] f16)
// ---------------------------------------------------------------------------
__global__ void convT_kernel(const float* __restrict__ in, __half* __restrict__ out,
                             int K, int N, int zeroFlag, int routeFlag,
                             const float* __restrict__ logits) {
    __shared__ float tile[64][33];
    const int e  = blockIdx.z;
    const int n0 = blockIdx.x * 32, k0 = blockIdx.y * 64;
    const float* ip = in  + (size_t)e * K * N;
    __half*      op = out + (size_t)e * N * K;
    const int tid = threadIdx.x;
#pragma unroll
    for (int i = 0; i < 8; i++) {
        int idx = i * 256 + tid, kk = idx >> 5, nn = idx & 31;
        tile[kk][nn] = ip[(size_t)(k0 + kk) * N + n0 + nn];
    }
    __syncthreads();
#pragma unroll
    for (int i = 0; i < 4; i++) {
        int idx = i * 256 + tid, nn = idx >> 5, kx = idx & 31;
        __half2 h = __floats2half2_rn(tile[2 * kx][nn], tile[2 * kx + 1][nn]);
        *(__half2*)(op + (size_t)(n0 + nn) * K + k0 + 2 * kx) = h;
    }

    if (zeroFlag && blockIdx.x == 0 && blockIdx.y == 0 && blockIdx.z == 0 && tid == 0) {
#pragma unroll
        for (int i = 0; i < NE; i++) { g_counts[i] = 0; g_fill[i] = 0; }
    }
    if (routeFlag && blockIdx.x == 0 && blockIdx.y == 0) {
        int t = blockIdx.z * 256 + tid;
        float l[NE];
#pragma unroll
        for (int i = 0; i < NE; i++) l[i] = logits[t * NE + i];
        int b0 = 0; float v0 = l[0];
#pragma unroll
        for (int i = 1; i < NE; i++) if (l[i] > v0) { v0 = l[i]; b0 = i; }
        int b1 = -1; float v1 = -1e30f;
#pragma unroll
        for (int i = 0; i < NE; i++) if (i != b0 && l[i] > v1) { v1 = l[i]; b1 = i; }
        float e1  = __expf(v1 - v0);
        float inv = 1.0f / (1.0f + e1);
        g_tok_e[t * 2 + 0] = b0; g_tok_s[t * 2 + 0] = inv;
        g_tok_e[t * 2 + 1] = b1; g_tok_s[t * 2 + 1] = e1 * inv;
        atomicAdd(&g_counts[b0], 1);
        atomicAdd(&g_counts[b1], 1);
    }
}

// ---------------------------------------------------------------------------
// scatter + permute: one block per token-expert pair.
// ---------------------------------------------------------------------------
__global__ void scatter_permute_kernel(const float* __restrict__ X) {
    __shared__ int s_pos;
    const int p = blockIdx.x;
    const int t = p >> 1;
    if (threadIdx.x == 0) {
        int e = g_tok_e[p];
        int s = 0, off = 0;
#pragma unroll
        for (int i = 0; i < NE; i++) { if (i == e) off = s; s += g_counts[i]; }
        int pos = off + atomicAdd(&g_fill[e], 1);
        g_tok_pos[p] = pos;
        s_pos = pos;
        if (p == 0) {
            int s2 = 0;
#pragma unroll
            for (int i = 0; i < NE; i++) { g_offsets[i] = s2; s2 += g_counts[i]; }
            g_offsets[NE] = s2;
        }
    }
    __syncthreads();
    const int pos = s_pos;
    const int c = threadIdx.x * 8;
    const float4* s = (const float4*)(X + (size_t)t * HID + c);
    float4 v0 = s[0], v1 = s[1];
    union { __half h[8]; uint4 u; } cv;
    cv.h[0] = __float2half_rn(v0.x); cv.h[1] = __float2half_rn(v0.y);
    cv.h[2] = __float2half_rn(v0.z); cv.h[3] = __float2half_rn(v0.w);
    cv.h[4] = __float2half_rn(v1.x); cv.h[5] = __float2half_rn(v1.y);
    cv.h[6] = __float2half_rn(v1.z); cv.h[7] = __float2half_rn(v1.w);
    *(uint4*)(g_Xp + (size_t)pos * HID + c) = cv.u;
}

// ---------------------------------------------------------------------------
// combine: out[t] = s0 * O2[pos0] + s1 * O2[pos1]
// ---------------------------------------------------------------------------
__global__ void combine_kernel(float* __restrict__ out) {
    const int t = blockIdx.x;
    const int c = threadIdx.x * 4;
    const int   p0 = g_tok_pos[2 * t],     p1 = g_tok_pos[2 * t + 1];
    const float s0 = g_tok_s[2 * t],       s1 = g_tok_s[2 * t + 1];
    float4 a = *(const float4*)(g_Out2 + (size_t)p0 * HID + c);
    float4 b = *(const float4*)(g_Out2 + (size_t)p1 * HID + c);
    float4 r;
    r.x = s0 * a.x + s1 * b.x;  r.y = s0 * a.y + s1 * b.y;
    r.z = s0 * a.z + s1 * b.z;  r.w = s0 * a.w + s1 * b.w;
    *(float4*)(out + (size_t)t * HID + c) = r;
}

// ---------------------------------------------------------------------------
// tcgen05 / TMA helpers (arch-specific pass only)
// ---------------------------------------------------------------------------
#if USE_TC
__device__ __forceinline__ void mbar_init(uint32_t a, uint32_t c) {
    asm volatile("mbarrier.init.shared.b64 [%0], %1;" :: "r"(a), "r"(c) : "memory");
}
__device__ __forceinline__ void mbar_expect_tx(uint32_t a, uint32_t bytes) {
    asm volatile("mbarrier.arrive.expect_tx.shared.b64 _, [%0], %1;"
                 :: "r"(a), "r"(bytes) : "memory");
}
__device__ __forceinline__ void mbar_wait(uint32_t a, uint32_t par) {
    asm volatile("{\n\t.reg .pred P;\n\tWL_%=:\n\t"
                 "mbarrier.try_wait.parity.acquire.cta.shared::cta.b64 P, [%0], %1, 0x989680;\n\t"
                 "@P bra WD_%=;\n\tbra WL_%=;\n\tWD_%=:\n\t}"
                 :: "r"(a), "r"(par) : "memory");
}
__device__ __forceinline__ void tma_2d(uint32_t dst, const CUtensorMap* map,
                                       int x, int y, uint32_t mbar) {
    asm volatile("cp.async.bulk.tensor.2d.shared::cta.global.tile.mbarrier::complete_tx::bytes "
                 "[%0], [%1, {%2, %3}], [%4];"
                 :: "r"(dst), "l"(map), "r"(x), "r"(y), "r"(mbar) : "memory");
}
__device__ __forceinline__ void tc_alloc(uint32_t slot, uint32_t n) {
    asm volatile("tcgen05.alloc.cta_group::1.sync.aligned.shared::cta.b32 [%0], %1;"
                 :: "r"(slot), "r"(n) : "memory");
}
__device__ __forceinline__ void tc_relinquish() {
    asm volatile("tcgen05.relinquish_alloc_permit.cta_group::1.sync.aligned;");
}
__device__ __forceinline__ void tc_dealloc(uint32_t t, uint32_t n) {
    asm volatile("tcgen05.dealloc.cta_group::1.sync.aligned.b32 %0, %1;" :: "r"(t), "r"(n));
}
__device__ __forceinline__ void tc_commit(uint32_t mbar) {
    asm volatile("tcgen05.commit.cta_group::1.mbarrier::arrive::one.shared::cluster.b64 [%0];"
                 :: "r"(mbar) : "memory");
}
__device__ __forceinline__ void tc_mma_f16_ss(uint32_t d, uint64_t ad, uint64_t bd,
                                              uint32_t idesc, uint32_t en) {
    asm volatile("{\n\t.reg .pred p;\n\tsetp.ne.u32 p, %4, 0;\n\t"
                 "tcgen05.mma.cta_group::1.kind::f16 [%0], %1, %2, %3, {%5,%5,%5,%5}, p;\n\t}"
                 :: "r"(d), "l"(ad), "l"(bd), "r"(idesc), "r"(en), "r"(0u) : "memory");
}
__device__ __forceinline__ void tc_fence_after()  { asm volatile("tcgen05.fence::after_thread_sync;"  ::: "memory"); }
__device__ __forceinline__ void tc_fence_before() { asm volatile("tcgen05.fence::before_thread_sync;" ::: "memory"); }
__device__ __forceinline__ void tc_wait_ld()      { asm volatile("tcgen05.wait::ld.sync.aligned;"     ::: "memory"); }

#define LDTM_X32(r, tmem_addr) \
    asm volatile( \
        "tcgen05.ld.sync.aligned.32x32b.x32.b32 " \
        "{%0, %1, %2, %3, %4, %5, %6, %7, " \
        " %8, %9, %10, %11, %12, %13, %14, %15, " \
        " %16, %17, %18, %19, %20, %21, %22, %23, " \
        " %24, %25, %26, %27, %28, %29, %30, %31}, [%32];" \
        : "=r"((r)[0]),  "=r"((r)[1]),  "=r"((r)[2]),  "=r"((r)[3]), \
          "=r"((r)[4]),  "=r"((r)[5]),  "=r"((r)[6]),  "=r"((r)[7]), \
          "=r"((r)[8]),  "=r"((r)[9]),  "=r"((r)[10]), "=r"((r)[11]), \
          "=r"((r)[12]), "=r"((r)[13]), "=r"((r)[14]), "=r"((r)[15]), \
          "=r"((r)[16]), "=r"((r)[17]), "=r"((r)[18]), "=r"((r)[19]), \
          "=r"((r)[20]), "=r"((r)[21]), "=r"((r)[22]), "=r"((r)[23]), \
          "=r"((r)[24]), "=r"((r)[25]), "=r"((r)[26]), "=r"((r)[27]), \
          "=r"((r)[28]), "=r"((r)[29]), "=r"((r)[30]), "=r"((r)[31]) \
        : "r"(tmem_addr))

// SMEM matrix descriptor: K-major SW128 (LBO=1, SBO=64, version=1, layout=2)
__device__ __forceinline__ uint64_t desc_k(uint32_t a) {
    return 0x4000404000010000ull | ((a >> 4) & 0x3FFF);
}
// idesc kind::f16: c=f32, a/b f16 K-major, M=128, N=128 (validated R10-R13)
#define MMA_IDESC_N128 0x8200010u
#endif // USE_TC

// ---------------------------------------------------------------------------
// Grouped GEMM. 256 threads, BM=256 (2 m-blocks share one B tile), N=128.
// Stage (48KB): A0 @0, A1 @16K, B @32K. ST=2. TMEM: mb*128 (256 cols).
//   MODE 0 (FC1+SwiGLU): grid (32, 16, 8); 64 act cols (proj+gate packed)
//   MODE 1 (FC2):        grid (8, 16, 8);  128 out cols -> g_Out2 fp32
// ---------------------------------------------------------------------------
template <int MODE>
__global__ __launch_bounds__(256)
void moe_gemm_kernel(const __grid_constant__ CUtensorMap tmA,
                     const __grid_constant__ CUtensorMap tmB) {
    const int e   = blockIdx.z;
    const int cnt = g_counts[e];
    const int mt  = blockIdx.y;
    if (mt * 256 >= cnt) return;
    const int bn      = blockIdx.x;
    const int rowbase = g_offsets[e] + mt * 256;
    const int rowlim  = g_offsets[e] + cnt;

    extern __shared__ __align__(1024) char smem[];
    const int tid = threadIdx.x, wid = tid >> 5, lane = tid & 31;

#if USE_TC
    constexpr int K     = MODE ? INTERD : HID;
    constexpr int KT    = K / 64;
    constexpr int ST    = 2;
    constexpr int STAGE = 49152;                      // A0 16K + A1 16K + B 16K
    constexpr int CTRL  = ST * STAGE;

    uint32_t sbase = (uint32_t)__cvta_generic_to_shared(smem);
    uint32_t barF[ST], barE[ST];
#pragma unroll
    for (int b = 0; b < ST; b++) {
        barF[b] = sbase + CTRL + 8 + b * 8;           // full: TMA complete_tx
        barE[b] = sbase + CTRL + 24 + b * 8;          // empty: tcgen05.commit
    }

    if (tid == 0) {
#pragma unroll
        for (int b = 0; b < ST; b++) { mbar_init(barF[b], 1); mbar_init(barE[b], 1); }
    }
    if (wid == 0) { tc_alloc(sbase + CTRL, 256); tc_relinquish(); }
    __syncthreads();
    uint32_t tmem = *(volatile uint32_t*)(smem + CTRL);

    if (tid == 0) {
        // ---- producer: TMA issue, gated on stage-empty (commit arrivals) ----
        for (int j = 0; j < KT; j++) {
            const int s = j % ST;
            if (j >= ST) mbar_wait(barE[s], ((j / ST) - 1) & 1);
            const uint32_t stg = sbase + s * STAGE;
            const int k0 = j * 64;
            mbar_expect_tx(barF[s], STAGE);
            tma_2d(stg,         &tmA, k0, rowbase,       barF[s]);   // A mb0
            tma_2d(stg + 16384, &tmA, k0, rowbase + 128, barF[s]);   // A mb1
            if (MODE == 0) {                                         // B: proj64+gate64
                tma_2d(stg + 32768, &tmB, k0, e * 4096 + bn * 64, barF[s]);
                tma_2d(stg + 40960, &tmB, k0, e * 4096 + INTERD + bn * 64, barF[s]);
            } else {                                                 // B: 128 out cols
                tma_2d(stg + 32768, &tmB, k0, e * HID + bn * 128, barF[s]);
            }
        }
        // tail: extend the sequential wait chain through the final ST commits
        for (int jj = KT; jj < KT + ST; jj++)
            mbar_wait(barE[jj % ST], ((jj / ST) - 1) & 1);
    } else if (tid == 32) {
        // ---- consumer: MMA issue, gated on stage-full; commit -> empty ----
        for (int kt = 0; kt < KT; kt++) {
            const int s = kt % ST;
            mbar_wait(barF[s], (kt / ST) & 1);
            const uint32_t stg = sbase + s * STAGE;
            uint64_t bd = desc_k(stg + 32768);
#pragma unroll
            for (int mb = 0; mb < 2; mb++) {
                uint64_t ad = desc_k(stg + mb * 16384);
#pragma unroll
                for (int k4 = 0; k4 < 4; k4++)
                    tc_mma_f16_ss(tmem + mb * 128, ad + 2 * k4, bd + 2 * k4,
                                  MMA_IDESC_N128, (kt > 0) || (k4 > 0));
            }
            tc_commit(barE[s]);
        }
    }
    // thread 0 arrives only after observing ALL commits complete
    __syncthreads();
    tc_fence_after();

    // epilogue: 8 warps; m-block = wid>>2, subpartition = wid&3
    {
        const int mb = wid >> 2, sp = wid & 3;
        const int m  = rowbase + mb * 128 + sp * 32 + lane;
        const int cb = mb * 128;
        if (MODE == 0) {
#pragma unroll
            for (int h = 0; h < 2; h++) {            // 2 x 32 act cols
                uint32_t dp[32], dg[32];
                LDTM_X32(dp, tmem + cb + h * 32);
                LDTM_X32(dg, tmem + cb + 64 + h * 32);
                tc_wait_ld();
                if (m < rowlim) {
                    uint32_t hh[16];
#pragma unroll
                    for (int j = 0; j < 32; j += 2) {
                        float p0 = __uint_as_float(dp[j]), p1 = __uint_as_float(dp[j + 1]);
                        float g0 = __uint_as_float(dg[j]), g1 = __uint_as_float(dg[j + 1]);
                        float a0 = p0 * g0 / (1.0f + __expf(-p0));
                        float a1 = p1 * g1 / (1.0f + __expf(-p1));
                        __half2 h2 = __floats2half2_rn(a0, a1);
                        hh[j >> 1] = *(uint32_t*)&h2;
                    }
                    uint4* dst = (uint4*)(g_Act + (size_t)m * INTERD + bn * 64 + h * 32);
#pragma unroll
                    for (int i = 0; i < 4; i++) dst[i] = ((uint4*)hh)[i];
                }
            }
        } else {
            float* orow = g_Out2 + (size_t)m * HID + bn * 128;
#pragma unroll
            for (int g4 = 0; g4 < 4; g4++) {         // 4 x 32 out cols
                uint32_t d[32];
                LDTM_X32(d, tmem + cb + g4 * 32);
                tc_wait_ld();
                if (m < rowlim) {
                    uint4* dst = (uint4*)(orow + g4 * 32);
#pragma unroll
                    for (int i = 0; i < 8; i++) dst[i] = ((uint4*)d)[i];
                }
            }
        }
        tc_fence_before();
    }
    __syncthreads();
    if (wid == 0) tc_dealloc(tmem, 256);

#else
    // ============ naive-correct fallback (insurance only) ============
    (void)smem; (void)wid; (void)lane; (void)tmA; (void)tmB;
    constexpr int K = MODE ? INTERD : HID;
    const __half* Ag = MODE ? g_Act : g_Xp;
    const __half* Wh = MODE ? (g_W2h + (size_t)e * HID * INTERD)
                            : (g_W1h + (size_t)e * 2 * INTERD * HID);
    for (int r256 = tid; r256 < 256; r256 += 256) {
        const int row = rowbase + r256;
        if (row >= rowlim) continue;
        if (MODE == 0) {
            const __half* a = Ag + (size_t)row * K;
            for (int j = 0; j < 64; j++) {
                const __half* wp = Wh + (size_t)(bn * 64 + j) * K;
                const __half* wg = Wh + (size_t)(INTERD + bn * 64 + j) * K;
                float p = 0.0f, g = 0.0f;
                for (int k = 0; k < K; k++) {
                    float av = __half2float(a[k]);
                    p += av * __half2float(wp[k]);
                    g += av * __half2float(wg[k]);
                }
                float act = p / (1.0f + __expf(-p)) * g;
                g_Act[(size_t)row * INTERD + bn * 64 + j] = __float2half_rn(act);
            }
        } else {
            const __half* a = Ag + (size_t)row * K;
            for (int j = 0; j < 128; j++) {
                const __half* wp = Wh + (size_t)(bn * 128 + j) * K;
                float s = 0.0f;
                for (int k = 0; k < K; k++)
                    s += __half2float(a[k]) * __half2float(wp[k]);
                g_Out2[(size_t)row * HID + bn * 128 + j] = s;
            }
        }
    }
#endif // USE_TC
}

// ---------------------------------------------------------------------------
// host: tensor map construction via runtime-fetched driver entry point
// ---------------------------------------------------------------------------
typedef CUresult (*PFN_encodeTiled)(
    CUtensorMap*, CUtensorMapDataType, cuuint32_t, void*,
    const cuuint64_t*, const cuuint64_t*, const cuuint32_t*, const cuuint32_t*,
    CUtensorMapInterleave, CUtensorMapSwizzle, CUtensorMapL2promotion,
    CUtensorMapFloatOOBfill);

static void make_map_2d(PFN_encodeTiled enc, CUtensorMap* m, void* base,
                        uint64_t dim0, uint64_t dim1, uint32_t box0, uint32_t box1) {
    cuuint64_t dims[2]    = {dim0, dim1};
    cuuint64_t strides[1] = {dim0 * 2};               // fp16 bytes per row
    cuuint32_t box[2]     = {box0, box1};
    cuuint32_t elem[2]    = {1, 1};
    enc(m, CU_TENSOR_MAP_DATA_TYPE_FLOAT16, 2, base, dims, strides, box, elem,
        CU_TENSOR_MAP_INTERLEAVE_NONE, CU_TENSOR_MAP_SWIZZLE_128B,
        CU_TENSOR_MAP_L2_PROMOTION_L2_128B, CU_TENSOR_MAP_FLOAT_OOB_FILL_NONE);
}

extern "C" void kernel_launch(void* const* d_in, const int* in_sizes, int n_in,
                              void* d_out, int out_size) {
    const float* X      = (const float*)d_in[0];  // [2048,1024]
    const float* logits = (const float*)d_in[1];  // [2048,8]
    const float* w1     = (const float*)d_in[2];  // [8,1024,4096]
    const float* w2     = (const float*)d_in[3];  // [8,2048,1024]
    float* out          = (float*)d_out;          // [2048,1024]

    void *xp = nullptr, *act = nullptr, *w1h = nullptr, *w2h = nullptr;
    cudaGetSymbolAddress(&xp,  g_Xp);
    cudaGetSymbolAddress(&act, g_Act);
    cudaGetSymbolAddress(&w1h, g_W1h);
    cudaGetSymbolAddress(&w2h, g_W2h);

    void* pfn = nullptr;
    cudaDriverEntryPointQueryResult qr;
    cudaGetDriverEntryPoint("cuTensorMapEncodeTiled", &pfn, cudaEnableDefault, &qr);
    PFN_encodeTiled enc = (PFN_encodeTiled)pfn;
    CUtensorMap mXP, mW1, mACT, mW2;
    make_map_2d(enc, &mXP,  xp,  HID,    NPP,             64, 128);
    make_map_2d(enc, &mW1,  w1h, HID,    NE * 2 * INTERD, 64, 64);
    make_map_2d(enc, &mACT, act, INTERD, NPP,             64, 128);
    make_map_2d(enc, &mW2,  w2h, INTERD, NE * HID,        64, 128);

    constexpr int SMEM = 2 * 49152 + 64;          // 98368 -> 2 CTAs/SM
    cudaFuncSetAttribute(moe_gemm_kernel<0>, cudaFuncAttributeMaxDynamicSharedMemorySize, SMEM);
    cudaFuncSetAttribute(moe_gemm_kernel<1>, cudaFuncAttributeMaxDynamicSharedMemorySize, SMEM);

    // 0: conv w1 (+ zero routing counters)
    convT_kernel<<<dim3(128, 16, NE), 256>>>(w1, (__half*)w1h, HID, 2 * INTERD, 1, 0, logits);
    // 1: conv w2 (+ top-2 routing in blocks x==0,y==0)
    convT_kernel<<<dim3(32, 32, NE), 256>>>(w2, (__half*)w2h, INTERD, HID, 0, 1, logits);
    // 2: scatter + permute (one block per pair)
    scatter_permute_kernel<<<NP, 128>>>(X);
    // 3: FC1 (+SwiGLU), BM=256 — ncu-profiled slot
    moe_gemm_kernel<0><<<dim3(32, 16, NE), 256, SMEM>>>(mXP, mW1);
    // 4: FC2 -> g_Out2, BM=256
    moe_gemm_kernel<1><<<dim3(8, 16, NE), 256, SMEM>>>(mACT, mW2);
    // 5: weighted combine
    combine_kernel<<<NT, 256>>>(out);
}

// round 15
// speedup vs baseline: 1.0549x; 1.0549x over previous
#include <cuda_runtime.h>
#include <cuda_fp16.h>
#include <cuda.h>
#include <cstdint>

// ---------------------------------------------------------------------------
// MoE (AriaExperts): top-2 routing + grouped tcgen05 f16 GEMM (SwiGLU fused)
// tokens=2048, hidden=1024, inter=2048, experts=8, topk=2
//
// R15: graph fork/join overlap. conv1 (s1) and conv2 (s2) run concurrently
// with zero/route/scatter on the main stream; FC1 joins e1, FC2 joins e2.
// FC1 = R14 config (BM=256, ST=2). FC2 = R13 config (BM=128, ST=3, better
// wave occupancy). All GEMM internals are the validated configurations.
// ---------------------------------------------------------------------------

#if defined(__CUDA_ARCH__) && \
    (defined(__CUDA_ARCH_FEAT_SM103_ALL) || \
     (defined(__CUDA_ARCH_SPECIFIC__)) || \
     (defined(__CUDA_ARCH_FAMILY_SPECIFIC__)))
#define USE_TC 1
#else
#define USE_TC 0
#endif

#define NT     2048
#define HID    1024
#define INTERD 2048
#define NE     8
#define TK     2
#define NP     (NT*TK)
#define NPP    (NP + 256)

// ---- device scratch ----
__device__ __align__(16) __half g_Xp  [NPP * HID];
__device__ __align__(16) __half g_Act [NPP * INTERD];
__device__ __align__(16) float  g_Out2[NPP * HID];
__device__ __align__(16) __half g_W1h[NE * 2 * INTERD * HID];   // [E][4096][1024] k-contig
__device__ __align__(16) __half g_W2h[NE * HID * INTERD];       // [E][1024][2048] k-contig
__device__ int   g_counts[NE];
__device__ int   g_fill[NE];
__device__ int   g_offsets[NE + 1];
__device__ int   g_tok_e[NT * TK];
__device__ float g_tok_s[NT * TK];
__device__ int   g_tok_pos[NT * TK];

// ---------------------------------------------------------------------------
// conv: weight transpose + fp32->fp16  (in [e][K][N] f32 -> out [e][N][K] f16)
// ---------------------------------------------------------------------------
__global__ void convT_kernel(const float* __restrict__ in, __half* __restrict__ out,
                             int K, int N) {
    __shared__ float tile[64][33];
    const int e  = blockIdx.z;
    const int n0 = blockIdx.x * 32, k0 = blockIdx.y * 64;
    const float* ip = in  + (size_t)e * K * N;
    __half*      op = out + (size_t)e * N * K;
    const int tid = threadIdx.x;
#pragma unroll
    for (int i = 0; i < 8; i++) {
        int idx = i * 256 + tid, kk = idx >> 5, nn = idx & 31;
        tile[kk][nn] = ip[(size_t)(k0 + kk) * N + n0 + nn];
    }
    __syncthreads();
#pragma unroll
    for (int i = 0; i < 4; i++) {
        int idx = i * 256 + tid, nn = idx >> 5, kx = idx & 31;
        __half2 h = __floats2half2_rn(tile[2 * kx][nn], tile[2 * kx + 1][nn]);
        *(__half2*)(op + (size_t)(n0 + nn) * K + k0 + 2 * kx) = h;
    }
}

// ---------------------------------------------------------------------------
// routing chain (main stream): zero -> route -> scatter+permute
// ---------------------------------------------------------------------------
__global__ void zero_kernel() {
    if (threadIdx.x < NE) { g_counts[threadIdx.x] = 0; g_fill[threadIdx.x] = 0; }
}

__global__ void route_kernel(const float* __restrict__ logits) {
    int t = blockIdx.x * blockDim.x + threadIdx.x;
    if (t >= NT) return;
    float l[NE];
#pragma unroll
    for (int i = 0; i < NE; i++) l[i] = logits[t * NE + i];
    int b0 = 0; float v0 = l[0];
#pragma unroll
    for (int i = 1; i < NE; i++) if (l[i] > v0) { v0 = l[i]; b0 = i; }
    int b1 = -1; float v1 = -1e30f;
#pragma unroll
    for (int i = 0; i < NE; i++) if (i != b0 && l[i] > v1) { v1 = l[i]; b1 = i; }
    float e1  = __expf(v1 - v0);
    float inv = 1.0f / (1.0f + e1);
    g_tok_e[t * 2 + 0] = b0; g_tok_s[t * 2 + 0] = inv;
    g_tok_e[t * 2 + 1] = b1; g_tok_s[t * 2 + 1] = e1 * inv;
    atomicAdd(&g_counts[b0], 1);
    atomicAdd(&g_counts[b1], 1);
}

__global__ void scatter_permute_kernel(const float* __restrict__ X) {
    __shared__ int s_pos;
    const int p = blockIdx.x;
    const int t = p >> 1;
    if (threadIdx.x == 0) {
        int e = g_tok_e[p];
        int s = 0, off = 0;
#pragma unroll
        for (int i = 0; i < NE; i++) { if (i == e) off = s; s += g_counts[i]; }
        int pos = off + atomicAdd(&g_fill[e], 1);
        g_tok_pos[p] = pos;
        s_pos = pos;
        if (p == 0) {
            int s2 = 0;
#pragma unroll
            for (int i = 0; i < NE; i++) { g_offsets[i] = s2; s2 += g_counts[i]; }
            g_offsets[NE] = s2;
        }
    }
    __syncthreads();
    const int pos = s_pos;
    const int c = threadIdx.x * 8;
    const float4* s = (const float4*)(X + (size_t)t * HID + c);
    float4 v0 = s[0], v1 = s[1];
    union { __half h[8]; uint4 u; } cv;
    cv.h[0] = __float2half_rn(v0.x); cv.h[1] = __float2half_rn(v0.y);
    cv.h[2] = __float2half_rn(v0.z); cv.h[3] = __float2half_rn(v0.w);
    cv.h[4] = __float2half_rn(v1.x); cv.h[5] = __float2half_rn(v1.y);
    cv.h[6] = __float2half_rn(v1.z); cv.h[7] = __float2half_rn(v1.w);
    *(uint4*)(g_Xp + (size_t)pos * HID + c) = cv.u;
}

// ---------------------------------------------------------------------------
// combine: out[t] = s0 * O2[pos0] + s1 * O2[pos1]
// ---------------------------------------------------------------------------
__global__ void combine_kernel(float* __restrict__ out) {
    const int t = blockIdx.x;
    const int c = threadIdx.x * 4;
    const int   p0 = g_tok_pos[2 * t],     p1 = g_tok_pos[2 * t + 1];
    const float s0 = g_tok_s[2 * t],       s1 = g_tok_s[2 * t + 1];
    float4 a = *(const float4*)(g_Out2 + (size_t)p0 * HID + c);
    float4 b = *(const float4*)(g_Out2 + (size_t)p1 * HID + c);
    float4 r;
    r.x = s0 * a.x + s1 * b.x;  r.y = s0 * a.y + s1 * b.y;
    r.z = s0 * a.z + s1 * b.z;  r.w = s0 * a.w + s1 * b.w;
    *(float4*)(out + (size_t)t * HID + c) = r;
}

// ---------------------------------------------------------------------------
// tcgen05 / TMA helpers (arch-specific pass only)
// ---------------------------------------------------------------------------
#if USE_TC
__device__ __forceinline__ void mbar_init(uint32_t a, uint32_t c) {
    asm volatile("mbarrier.init.shared.b64 [%0], %1;" :: "r"(a), "r"(c) : "memory");
}
__device__ __forceinline__ void mbar_expect_tx(uint32_t a, uint32_t bytes) {
    asm volatile("mbarrier.arrive.expect_tx.shared.b64 _, [%0], %1;"
                 :: "r"(a), "r"(bytes) : "memory");
}
__device__ __forceinline__ void mbar_wait(uint32_t a, uint32_t par) {
    asm volatile("{\n\t.reg .pred P;\n\tWL_%=:\n\t"
                 "mbarrier.try_wait.parity.acquire.cta.shared::cta.b64 P, [%0], %1, 0x989680;\n\t"
                 "@P bra WD_%=;\n\tbra WL_%=;\n\tWD_%=:\n\t}"
                 :: "r"(a), "r"(par) : "memory");
}
__device__ __forceinline__ void tma_2d(uint32_t dst, const CUtensorMap* map,
                                       int x, int y, uint32_t mbar) {
    asm volatile("cp.async.bulk.tensor.2d.shared::cta.global.tile.mbarrier::complete_tx::bytes "
                 "[%0], [%1, {%2, %3}], [%4];"
                 :: "r"(dst), "l"(map), "r"(x), "r"(y), "r"(mbar) : "memory");
}
__device__ __forceinline__ void tc_alloc(uint32_t slot, uint32_t n) {
    asm volatile("tcgen05.alloc.cta_group::1.sync.aligned.shared::cta.b32 [%0], %1;"
                 :: "r"(slot), "r"(n) : "memory");
}
__device__ __forceinline__ void tc_relinquish() {
    asm volatile("tcgen05.relinquish_alloc_permit.cta_group::1.sync.aligned;");
}
__device__ __forceinline__ void tc_dealloc(uint32_t t, uint32_t n) {
    asm volatile("tcgen05.dealloc.cta_group::1.sync.aligned.b32 %0, %1;" :: "r"(t), "r"(n));
}
__device__ __forceinline__ void tc_commit(uint32_t mbar) {
    asm volatile("tcgen05.commit.cta_group::1.mbarrier::arrive::one.shared::cluster.b64 [%0];"
                 :: "r"(mbar) : "memory");
}
__device__ __forceinline__ void tc_mma_f16_ss(uint32_t d, uint64_t ad, uint64_t bd,
                                              uint32_t idesc, uint32_t en) {
    asm volatile("{\n\t.reg .pred p;\n\tsetp.ne.u32 p, %4, 0;\n\t"
                 "tcgen05.mma.cta_group::1.kind::f16 [%0], %1, %2, %3, {%5,%5,%5,%5}, p;\n\t}"
                 :: "r"(d), "l"(ad), "l"(bd), "r"(idesc), "r"(en), "r"(0u) : "memory");
}
__device__ __forceinline__ void tc_fence_after()  { asm volatile("tcgen05.fence::after_thread_sync;"  ::: "memory"); }
__device__ __forceinline__ void tc_fence_before() { asm volatile("tcgen05.fence::before_thread_sync;" ::: "memory"); }
__device__ __forceinline__ void tc_wait_ld()      { asm volatile("tcgen05.wait::ld.sync.aligned;"     ::: "memory"); }

#define LDTM_X32(r, tmem_addr) \
    asm volatile( \
        "tcgen05.ld.sync.aligned.32x32b.x32.b32 " \
        "{%0, %1, %2, %3, %4, %5, %6, %7, " \
        " %8, %9, %10, %11, %12, %13, %14, %15, " \
        " %16, %17, %18, %19, %20, %21, %22, %23, " \
        " %24, %25, %26, %27, %28, %29, %30, %31}, [%32];" \
        : "=r"((r)[0]),  "=r"((r)[1]),  "=r"((r)[2]),  "=r"((r)[3]), \
          "=r"((r)[4]),  "=r"((r)[5]),  "=r"((r)[6]),  "=r"((r)[7]), \
          "=r"((r)[8]),  "=r"((r)[9]),  "=r"((r)[10]), "=r"((r)[11]), \
          "=r"((r)[12]), "=r"((r)[13]), "=r"((r)[14]), "=r"((r)[15]), \
          "=r"((r)[16]), "=r"((r)[17]), "=r"((r)[18]), "=r"((r)[19]), \
          "=r"((r)[20]), "=r"((r)[21]), "=r"((r)[22]), "=r"((r)[23]), \
          "=r"((r)[24]), "=r"((r)[25]), "=r"((r)[26]), "=r"((r)[27]), \
          "=r"((r)[28]), "=r"((r)[29]), "=r"((r)[30]), "=r"((r)[31]) \
        : "r"(tmem_addr))

// SMEM matrix descriptor: K-major SW128 (LBO=1, SBO=64, version=1, layout=2)
__device__ __forceinline__ uint64_t desc_k(uint32_t a) {
    return 0x4000404000010000ull | ((a >> 4) & 0x3FFF);
}
// idesc kind::f16: c=f32, a/b f16 K-major, M=128, N=128 (validated R10-R14)
#define MMA_IDESC_N128 0x8200010u
#endif // USE_TC

// ---------------------------------------------------------------------------
// FC1 GEMM (R14 config): BM=256, ST=2, stage 48KB, TMEM 256 cols.
// grid (32, 16, 8); 64 act cols (proj+gate packed as N=128 B tile)
// ---------------------------------------------------------------------------
__global__ __launch_bounds__(256)
void moe_gemm_fc1(const __grid_constant__ CUtensorMap tmA,
                  const __grid_constant__ CUtensorMap tmB) {
    const int e   = blockIdx.z;
    const int cnt = g_counts[e];
    const int mt  = blockIdx.y;
    if (mt * 256 >= cnt) return;
    const int bn      = blockIdx.x;
    const int rowbase = g_offsets[e] + mt * 256;
    const int rowlim  = g_offsets[e] + cnt;

    extern __shared__ __align__(1024) char smem[];
    const int tid = threadIdx.x, wid = tid >> 5, lane = tid & 31;

#if USE_TC
    constexpr int KT    = HID / 64;                   // 16
    constexpr int ST    = 2;
    constexpr int STAGE = 49152;                      // A0 16K + A1 16K + B 16K
    constexpr int CTRL  = ST * STAGE;

    uint32_t sbase = (uint32_t)__cvta_generic_to_shared(smem);
    uint32_t barF[ST], barE[ST];
#pragma unroll
    for (int b = 0; b < ST; b++) {
        barF[b] = sbase + CTRL + 8 + b * 8;
        barE[b] = sbase + CTRL + 24 + b * 8;
    }
    if (tid == 0) {
#pragma unroll
        for (int b = 0; b < ST; b++) { mbar_init(barF[b], 1); mbar_init(barE[b], 1); }
    }
    if (wid == 0) { tc_alloc(sbase + CTRL, 256); tc_relinquish(); }
    __syncthreads();
    uint32_t tmem = *(volatile uint32_t*)(smem + CTRL);

    if (tid == 0) {
        for (int j = 0; j < KT; j++) {
            const int s = j % ST;
            if (j >= ST) mbar_wait(barE[s], ((j / ST) - 1) & 1);
            const uint32_t stg = sbase + s * STAGE;
            const int k0 = j * 64;
            mbar_expect_tx(barF[s], STAGE);
            tma_2d(stg,         &tmA, k0, rowbase,       barF[s]);
            tma_2d(stg + 16384, &tmA, k0, rowbase + 128, barF[s]);
            tma_2d(stg + 32768, &tmB, k0, e * 4096 + bn * 64, barF[s]);
            tma_2d(stg + 40960, &tmB, k0, e * 4096 + INTERD + bn * 64, barF[s]);
        }
        for (int jj = KT; jj < KT + ST; jj++)
            mbar_wait(barE[jj % ST], ((jj / ST) - 1) & 1);
    } else if (tid == 32) {
        for (int kt = 0; kt < KT; kt++) {
            const int s = kt % ST;
            mbar_wait(barF[s], (kt / ST) & 1);
            const uint32_t stg = sbase + s * STAGE;
            uint64_t bd = desc_k(stg + 32768);
#pragma unroll
            for (int mb = 0; mb < 2; mb++) {
                uint64_t ad = desc_k(stg + mb * 16384);
#pragma unroll
                for (int k4 = 0; k4 < 4; k4++)
                    tc_mma_f16_ss(tmem + mb * 128, ad + 2 * k4, bd + 2 * k4,
                                  MMA_IDESC_N128, (kt > 0) || (k4 > 0));
            }
            tc_commit(barE[s]);
        }
    }
    __syncthreads();
    tc_fence_after();

    {
        const int mb = wid >> 2, sp = wid & 3;
        const int m  = rowbase + mb * 128 + sp * 32 + lane;
        const int cb = mb * 128;
#pragma unroll
        for (int h = 0; h < 2; h++) {
            uint32_t dp[32], dg[32];
            LDTM_X32(dp, tmem + cb + h * 32);
            LDTM_X32(dg, tmem + cb + 64 + h * 32);
            tc_wait_ld();
            if (m < rowlim) {
                uint32_t hh[16];
#pragma unroll
                for (int j = 0; j < 32; j += 2) {
                    float p0 = __uint_as_float(dp[j]), p1 = __uint_as_float(dp[j + 1]);
                    float g0 = __uint_as_float(dg[j]), g1 = __uint_as_float(dg[j + 1]);
                    float a0 = p0 * g0 / (1.0f + __expf(-p0));
                    float a1 = p1 * g1 / (1.0f + __expf(-p1));
                    __half2 h2 = __floats2half2_rn(a0, a1);
                    hh[j >> 1] = *(uint32_t*)&h2;
                }
                uint4* dst = (uint4*)(g_Act + (size_t)m * INTERD + bn * 64 + h * 32);
#pragma unroll
                for (int i = 0; i < 4; i++) dst[i] = ((uint4*)hh)[i];
            }
        }
        tc_fence_before();
    }
    __syncthreads();
    if (wid == 0) tc_dealloc(tmem, 256);
#else
    (void)smem; (void)wid; (void)lane; (void)tmA; (void)tmB;
    const __half* Wh = g_W1h + (size_t)e * 2 * INTERD * HID;
    for (int r = tid; r < 256; r += 256) {
        const int row = rowbase + r;
        if (row >= rowlim) continue;
        const __half* a = g_Xp + (size_t)row * HID;
        for (int j = 0; j < 64; j++) {
            const __half* wp = Wh + (size_t)(bn * 64 + j) * HID;
            const __half* wg = Wh + (size_t)(INTERD + bn * 64 + j) * HID;
            float p = 0.0f, g = 0.0f;
            for (int k = 0; k < HID; k++) {
                float av = __half2float(a[k]);
                p += av * __half2float(wp[k]);
                g += av * __half2float(wg[k]);
            }
            g_Act[(size_t)row * INTERD + bn * 64 + j] =
                __float2half_rn(p / (1.0f + __expf(-p)) * g);
        }
    }
#endif
}

// ---------------------------------------------------------------------------
// FC2 GEMM (R13 config): BM=128, ST=3, stage 32KB, TMEM 128 cols.
// grid (8, 32, 8); 128 out cols -> g_Out2 fp32
// ---------------------------------------------------------------------------
__global__ __launch_bounds__(256)
void moe_gemm_fc2(const __grid_constant__ CUtensorMap tmA,
                  const __grid_constant__ CUtensorMap tmB) {
    const int e   = blockIdx.z;
    const int cnt = g_counts[e];
    const int mt  = blockIdx.y;
    if (mt * 128 >= cnt) return;
    const int bn      = blockIdx.x;
    const int rowbase = g_offsets[e] + mt * 128;
    const int rowlim  = g_offsets[e] + cnt;

    extern __shared__ __align__(1024) char smem[];
    const int tid = threadIdx.x, wid = tid >> 5, lane = tid & 31;

#if USE_TC
    constexpr int KT    = INTERD / 64;                // 32
    constexpr int ST    = 3;
    constexpr int STAGE = 32768;                      // A 16K + B 16K
    constexpr int CTRL  = ST * STAGE;

    uint32_t sbase = (uint32_t)__cvta_generic_to_shared(smem);
    uint32_t barF[ST], barE[ST];
#pragma unroll
    for (int b = 0; b < ST; b++) {
        barF[b] = sbase + CTRL + 8 + b * 8;
        barE[b] = sbase + CTRL + 32 + b * 8;
    }
    if (tid == 0) {
#pragma unroll
        for (int b = 0; b < ST; b++) { mbar_init(barF[b], 1); mbar_init(barE[b], 1); }
    }
    if (wid == 0) { tc_alloc(sbase + CTRL, 128); tc_relinquish(); }
    __syncthreads();
    uint32_t tmem = *(volatile uint32_t*)(smem + CTRL);

    if (tid == 0) {
        for (int j = 0; j < KT; j++) {
            const int s = j % ST;
            if (j >= ST) mbar_wait(barE[s], ((j / ST) - 1) & 1);
            const uint32_t stg = sbase + s * STAGE;
            const int k0 = j * 64;
            mbar_expect_tx(barF[s], STAGE);
            tma_2d(stg,         &tmA, k0, rowbase, barF[s]);
            tma_2d(stg + 16384, &tmB, k0, e * HID + bn * 128, barF[s]);
        }
        for (int jj = KT; jj < KT + ST; jj++)
            mbar_wait(barE[jj % ST], ((jj / ST) - 1) & 1);
    } else if (tid == 32) {
        for (int kt = 0; kt < KT; kt++) {
            const int s = kt % ST;
            mbar_wait(barF[s], (kt / ST) & 1);
            const uint32_t stg = sbase + s * STAGE;
            uint64_t ad = desc_k(stg);
            uint64_t bd = desc_k(stg + 16384);
#pragma unroll
            for (int k4 = 0; k4 < 4; k4++)
                tc_mma_f16_ss(tmem, ad + 2 * k4, bd + 2 * k4,
                              MMA_IDESC_N128, (kt > 0) || (k4 > 0));
            tc_commit(barE[s]);
        }
    }
    __syncthreads();
    tc_fence_after();

    {
        const int sp = wid & 3, hp = wid >> 2;
        const int m  = rowbase + sp * 32 + lane;
        float* orow = g_Out2 + (size_t)m * HID + bn * 128 + hp * 64;
#pragma unroll
        for (int half = 0; half < 2; half++) {
            uint32_t d[32];
            LDTM_X32(d, tmem + hp * 64 + half * 32);
            tc_wait_ld();
            if (m < rowlim) {
                uint4* dst = (uint4*)(orow + half * 32);
#pragma unroll
                for (int i = 0; i < 8; i++) dst[i] = ((uint4*)d)[i];
            }
        }
        tc_fence_before();
    }
    __syncthreads();
    if (wid == 0) tc_dealloc(tmem, 128);
#else
    (void)smem; (void)wid; (void)lane; (void)tmA; (void)tmB;
    const __half* Wh = g_W2h + (size_t)e * HID * INTERD;
    if (tid >= 128) return;
    const int row = rowbase + tid;
    if (row >= rowlim) return;
    const __half* a = g_Act + (size_t)row * INTERD;
    for (int j = 0; j < 128; j++) {
        const __half* wp = Wh + (size_t)(bn * 128 + j) * INTERD;
        float s = 0.0f;
        for (int k = 0; k < INTERD; k++)
            s += __half2float(a[k]) * __half2float(wp[k]);
        g_Out2[(size_t)row * HID + bn * 128 + j] = s;
    }
#endif
}

// ---------------------------------------------------------------------------
// host: tensor maps + fork/join stream plumbing
// ---------------------------------------------------------------------------
typedef CUresult (*PFN_encodeTiled)(
    CUtensorMap*, CUtensorMapDataType, cuuint32_t, void*,
    const cuuint64_t*, const cuuint64_t*, const cuuint32_t*, const cuuint32_t*,
    CUtensorMapInterleave, CUtensorMapSwizzle, CUtensorMapL2promotion,
    CUtensorMapFloatOOBfill);

static void make_map_2d(PFN_encodeTiled enc, CUtensorMap* m, void* base,
                        uint64_t dim0, uint64_t dim1, uint32_t box0, uint32_t box1) {
    cuuint64_t dims[2]    = {dim0, dim1};
    cuuint64_t strides[1] = {dim0 * 2};
    cuuint32_t box[2]     = {box0, box1};
    cuuint32_t elem[2]    = {1, 1};
    enc(m, CU_TENSOR_MAP_DATA_TYPE_FLOAT16, 2, base, dims, strides, box, elem,
        CU_TENSOR_MAP_INTERLEAVE_NONE, CU_TENSOR_MAP_SWIZZLE_128B,
        CU_TENSOR_MAP_L2_PROMOTION_L2_128B, CU_TENSOR_MAP_FLOAT_OOB_FILL_NONE);
}

extern "C" void kernel_launch(void* const* d_in, const int* in_sizes, int n_in,
                              void* d_out, int out_size) {
    const float* X      = (const float*)d_in[0];  // [2048,1024]
    const float* logits = (const float*)d_in[1];  // [2048,8]
    const float* w1     = (const float*)d_in[2];  // [8,1024,4096]
    const float* w2     = (const float*)d_in[3];  // [8,2048,1024]
    float* out          = (float*)d_out;          // [2048,1024]

    void *xp = nullptr, *act = nullptr, *w1h = nullptr, *w2h = nullptr;
    cudaGetSymbolAddress(&xp,  g_Xp);
    cudaGetSymbolAddress(&act, g_Act);
    cudaGetSymbolAddress(&w1h, g_W1h);
    cudaGetSymbolAddress(&w2h, g_W2h);

    void* pfn = nullptr;
    cudaDriverEntryPointQueryResult qr;
    cudaGetDriverEntryPoint("cuTensorMapEncodeTiled", &pfn, cudaEnableDefault, &qr);
    PFN_encodeTiled enc = (PFN_encodeTiled)pfn;
    CUtensorMap mXP, mW1, mACT, mW2;
    make_map_2d(enc, &mXP,  xp,  HID,    NPP,             64, 128);
    make_map_2d(enc, &mW1,  w1h, HID,    NE * 2 * INTERD, 64, 64);
    make_map_2d(enc, &mACT, act, INTERD, NPP,             64, 128);
    make_map_2d(enc, &mW2,  w2h, INTERD, NE * HID,        64, 128);

    constexpr int SMEM1 = 2 * 49152 + 64;         // 98368 (FC1) -> 2 CTAs/SM
    constexpr int SMEM2 = 3 * 32768 + 64;         // 98368 (FC2) -> 2 CTAs/SM
    cudaFuncSetAttribute(moe_gemm_fc1, cudaFuncAttributeMaxDynamicSharedMemorySize, SMEM1);
    cudaFuncSetAttribute(moe_gemm_fc2, cudaFuncAttributeMaxDynamicSharedMemorySize, SMEM2);

    // streams/events created once (host-side objects; no device allocation)
    static cudaStream_t s1 = nullptr, s2 = nullptr;
    static cudaEvent_t ev0 = nullptr, ev1 = nullptr, ev2 = nullptr;
    if (s1 == nullptr) {
        cudaStreamCreateWithFlags(&s1, cudaStreamNonBlocking);
        cudaStreamCreateWithFlags(&s2, cudaStreamNonBlocking);
        cudaEventCreateWithFlags(&ev0, cudaEventDisableTiming);
        cudaEventCreateWithFlags(&ev1, cudaEventDisableTiming);
        cudaEventCreateWithFlags(&ev2, cudaEventDisableTiming);
    }

    // fork: conv1 on s1, conv2 on s2; routing chain stays on the main stream
    cudaEventRecord(ev0, 0);
    cudaStreamWaitEvent(s1, ev0, 0);
    cudaStreamWaitEvent(s2, ev0, 0);

    convT_kernel<<<dim3(128, 16, NE), 256, 0, s1>>>(w1, (__half*)w1h, HID, 2 * INTERD);
    cudaEventRecord(ev1, s1);
    convT_kernel<<<dim3(32, 32, NE), 256, 0, s2>>>(w2, (__half*)w2h, INTERD, HID);
    cudaEventRecord(ev2, s2);

    zero_kernel<<<1, 32>>>();
    route_kernel<<<NT / 256, 256>>>(logits);
    scatter_permute_kernel<<<NP, 128>>>(X);

    // join conv1 -> FC1
    cudaStreamWaitEvent(0, ev1, 0);
    moe_gemm_fc1<<<dim3(32, 16, NE), 256, SMEM1>>>(mXP, mW1);
    // join conv2 -> FC2
    cudaStreamWaitEvent(0, ev2, 0);
    moe_gemm_fc2<<<dim3(8, 32, NE), 256, SMEM2>>>(mACT, mW2);

    combine_kernel<<<NT, 256>>>(out);
}